// round 8
// baseline (speedup 1.0000x reference)
#include <cuda_runtime.h>
#include <cuda_bf16.h>
#include <cstdint>

// Problem constants (fixed by setup_inputs):
//   x: [65536, 256] f32,  A: [256, 1024] f32
//   out: [1024, 256, 256] f32  (G=1024 blocks of 256x256)
#define B_ROWS  65536
#define DIM     256            // K
#define HDIM    1024           // N total
#define MTILE   128            // rows per CTA
#define NCH     64             // N per chunk
#define NCHUNKS (HDIM / NCH)   // 16
#define NCTAS   (B_ROWS / MTILE) // 512

#define SKP     264                    // bf16 elems per padded SMEM row (528 B; odd 16B stride -> conflict-free)
#define SKPB    (SKP * 2)              // 528 bytes
#define ABYTES  (NCH * SKPB)           // 33792
#define SMEM_BYTES (2 * ABYTES)        // 67584  -> 3 CTAs/SM (SMEM 203KB, RF 84 regs)

// Device scratch: A^T in bf16, [N=1024][K=256] row-major
__device__ __nv_bfloat16 g_At[HDIM * DIM];

// ---------------- helpers ----------------
__device__ __forceinline__ uint32_t smem_u32(const void* p) {
    uint32_t a;
    asm("{ .reg .u64 t; cvta.to.shared.u64 t, %1; cvt.u32.u64 %0, t; }"
        : "=r"(a) : "l"(p));
    return a;
}

#define LDSM4(r0, r1, r2, r3, addr) \
    asm volatile("ldmatrix.sync.aligned.m8n8.x4.shared.b16 {%0,%1,%2,%3}, [%4];" \
                 : "=r"(r0), "=r"(r1), "=r"(r2), "=r"(r3) : "r"(addr))

#define MMA16816(c, a0, a1, a2, a3, b0, b1) \
    asm volatile("mma.sync.aligned.m16n8k16.row.col.f32.bf16.bf16.f32 " \
                 "{%0,%1,%2,%3}, {%4,%5,%6,%7}, {%8,%9}, {%0,%1,%2,%3};" \
                 : "+f"((c)[0]), "+f"((c)[1]), "+f"((c)[2]), "+f"((c)[3]) \
                 : "r"(a0), "r"(a1), "r"(a2), "r"(a3), "r"(b0), "r"(b1))

__device__ __forceinline__ float silu_f(float z) {
    float h = 0.5f * z;
    float t;
    asm("tanh.approx.f32 %0, %1;" : "=f"(t) : "f"(h));
    return fmaf(h, t, h);      // 0.5z + 0.5z*tanh(z/2) = silu(z)
}

__device__ __forceinline__ uint32_t pack_bf16x2(float a, float b) {
    __nv_bfloat162 h = __float22bfloat162_rn(make_float2(a, b));
    return *(uint32_t*)&h;
}

// ---------------- A transpose+convert: A[k][n] f32 -> g_At[n][k] bf16 ----------------
__global__ void cvt_A_kernel(const float* __restrict__ A) {
    __shared__ float tile[32][33];
    int n0 = blockIdx.x * 32;
    int k0 = blockIdx.y * 32;
    int tx = threadIdx.x, ty = threadIdx.y;   // block (32, 8)
#pragma unroll
    for (int r = 0; r < 32; r += 8)
        tile[ty + r][tx] = A[(size_t)(k0 + ty + r) * HDIM + n0 + tx];
    __syncthreads();
#pragma unroll
    for (int r = 0; r < 32; r += 8)
        g_At[(size_t)(n0 + ty + r) * DIM + k0 + tx] = __float2bfloat16_rn(tile[tx][ty + r]);
}

// ---------------- fused GEMM(bf16 HMMA) + silu-rowsum + zero-fill + scatter ----------------
__global__ __launch_bounds__(256, 3)
void gemm_silu_kernel(const float* __restrict__ x, float* __restrict__ out) {
    extern __shared__ char smem_raw[];
    __shared__ float red[128];
    const uint32_t sa0 = smem_u32(smem_raw);

    const int tid  = threadIdx.x;
    const int wid  = tid >> 5;        // 8 warps; warp w owns m-rows [16w, 16w+16)
    const int lane = tid & 31;
    const int ct   = blockIdx.x;
    const size_t b0 = (size_t)ct * MTILE;

    // ---- 1) zero-fill this CTA's 512KB output region (2 G-blocks); stores drain in background ----
    {
        float4 z4 = make_float4(0.f, 0.f, 0.f, 0.f);
        float4* zq = (float4*)(out + (size_t)ct * 131072);
#pragma unroll 4
        for (int j = 0; j < 128; j++) zq[tid + j * 256] = z4;
    }

    // ---- 2) prefetch At chunk 0 via cp.async ----
    {
#pragma unroll
        for (int j = 0; j < 8; j++) {
            int idx = tid + j * 256;          // 2048 x 16B
            int nl  = idx >> 5;               // 32 16B-chunks per row
            int kc  = idx & 31;
            uint32_t dst = sa0 + (uint32_t)nl * SKPB + (uint32_t)kc * 16;
            uint64_t src = __cvta_generic_to_global(g_At + (size_t)nl * DIM + kc * 8);
            asm volatile("cp.async.cg.shared.global [%0], [%1], 16;" :: "r"(dst), "l"(src));
        }
        asm volatile("cp.async.commit_group;" ::: "memory");
    }

    // x rows this thread's A-fragments come from (m16n8k16: g = lane>>2, q = lane&3)
    const int g = lane >> 2, q = lane & 3;
    const float* xr0 = x + (b0 + (size_t)(wid * 16 + g)) * DIM;   // m_lo row
    const float* xr1 = xr0 + 8 * DIM;                             // m_hi row

    float rs0 = 0.f, rs1 = 0.f;   // row sums for m = 16w+g and 16w+g+8

    // ---- 3) n-chunk loop ----
    const int brow = lane & 7, bmat = lane >> 3;
    for (int c = 0; c < NCHUNKS; c++) {
        if (c + 1 < NCHUNKS) {
            uint32_t sa_n = sa0 + (uint32_t)((c + 1) & 1) * ABYTES;
#pragma unroll
            for (int j = 0; j < 8; j++) {
                int idx = tid + j * 256;
                int nl  = idx >> 5;
                int kc  = idx & 31;
                uint32_t dst = sa_n + (uint32_t)nl * SKPB + (uint32_t)kc * 16;
                uint64_t src = __cvta_generic_to_global(
                    g_At + (size_t)((c + 1) * NCH + nl) * DIM + kc * 8);
                asm volatile("cp.async.cg.shared.global [%0], [%1], 16;" :: "r"(dst), "l"(src));
            }
            asm volatile("cp.async.commit_group;" ::: "memory");
            asm volatile("cp.async.wait_group 1;" ::: "memory");
        } else {
            asm volatile("cp.async.wait_group 0;" ::: "memory");
        }
        __syncthreads();

        const uint32_t sa = sa0 + (uint32_t)(c & 1) * ABYTES;
        const uint32_t bbase = sa + (uint32_t)brow * SKPB + (uint32_t)bmat * 16;

        // half = group of 4 n8-blocks; pass = K half (128). acc persists across passes.
#pragma unroll
        for (int half = 0; half < 2; half++) {
            float acc[4][4];
#pragma unroll
            for (int nb = 0; nb < 4; nb++) {
                acc[nb][0] = 0.f; acc[nb][1] = 0.f; acc[nb][2] = 0.f; acc[nb][3] = 0.f;
            }
#pragma unroll
            for (int pass = 0; pass < 2; pass++) {
                // af for this K-half: 8 k16-fragments (32 regs), straight from global x
                uint32_t af[8][4];
#pragma unroll
                for (int f = 0; f < 8; f++) {
                    int k0 = pass * 128 + f * 16 + 2 * q;
                    float2 v00 = *(const float2*)(xr0 + k0);
                    float2 v10 = *(const float2*)(xr1 + k0);
                    float2 v01 = *(const float2*)(xr0 + k0 + 8);
                    float2 v11 = *(const float2*)(xr1 + k0 + 8);
                    af[f][0] = pack_bf16x2(v00.x, v00.y);
                    af[f][1] = pack_bf16x2(v10.x, v10.y);
                    af[f][2] = pack_bf16x2(v01.x, v01.y);
                    af[f][3] = pack_bf16x2(v11.x, v11.y);
                }
                // 16 steps: p = nb*4 + t  (t = k32 index within pass)
                // B addr(p) = bbase + (half*4 + nb)*8*SKPB + (pass*4 + t)*64
                uint32_t bb[3][4];
                {
                    const uint32_t a0 = bbase + (uint32_t)(half * 4) * 8u * SKPB
                                      + (uint32_t)(pass * 4) * 64u;
                    LDSM4(bb[0][0], bb[0][1], bb[0][2], bb[0][3], a0);          // p=0
                    LDSM4(bb[1][0], bb[1][1], bb[1][2], bb[1][3], a0 + 64u);    // p=1
                }
#pragma unroll
                for (int nb = 0; nb < 4; nb++) {
#pragma unroll
                    for (int t = 0; t < 4; t++) {
                        const int p = nb * 4 + t;
                        const int cur = p % 3;
                        if (p + 2 < 16) {
                            const int pn = p + 2;
                            const int s  = pn % 3;
                            const uint32_t addr = bbase
                                + (uint32_t)(half * 4 + (pn >> 2)) * 8u * SKPB
                                + (uint32_t)(pass * 4 + (pn & 3)) * 64u;
                            LDSM4(bb[s][0], bb[s][1], bb[s][2], bb[s][3], addr);
                        }
                        MMA16816(acc[nb], af[2 * t][0],     af[2 * t][1],
                                          af[2 * t][2],     af[2 * t][3],
                                          bb[cur][0], bb[cur][1]);
                        MMA16816(acc[nb], af[2 * t + 1][0], af[2 * t + 1][1],
                                          af[2 * t + 1][2], af[2 * t + 1][3],
                                          bb[cur][2], bb[cur][3]);
                    }
                }
            }
#pragma unroll
            for (int nb = 0; nb < 4; nb++) {
                rs0 += silu_f(acc[nb][0]) + silu_f(acc[nb][1]);
                rs1 += silu_f(acc[nb][2]) + silu_f(acc[nb][3]);
            }
        }
        __syncthreads();   // buffer (c&1) may be overwritten by next iteration's prefetch
    }

    // ---- 4) reduce across the 4 threads of each mma group, stage to shared ----
    rs0 += __shfl_xor_sync(0xFFFFFFFFu, rs0, 1);
    rs0 += __shfl_xor_sync(0xFFFFFFFFu, rs0, 2);
    rs1 += __shfl_xor_sync(0xFFFFFFFFu, rs1, 1);
    rs1 += __shfl_xor_sync(0xFFFFFFFFu, rs1, 2);
    if ((lane & 3) == 0) {
        red[wid * 16 + g]     = rs0;
        red[wid * 16 + g + 8] = rs1;
    }
    __syncthreads();

    // ---- 5) scatter +/- s onto the block anti-diagonals (region already zeroed by this CTA) ----
    if (tid < 128) {
        float s = red[tid];
        size_t b = b0 + (size_t)tid;
        size_t gb = b >> 6;                // G block (64 rows per block)
        int i2 = (int)(b & 63) * 2;
        float* og = out + gb * 65536;
        og[(size_t)i2 * 256 + 128 + i2]       =  s;   // top-right diag, even
        og[(size_t)(i2 + 1) * 256 + 129 + i2] =  s;   // top-right diag, odd
        og[(size_t)(128 + i2) * 256 + i2]     = -s;   // bottom-left diag, even
        og[(size_t)(129 + i2) * 256 + i2 + 1] = -s;   // bottom-left diag, odd
    }
}

// ---------------- launch ----------------
extern "C" void kernel_launch(void* const* d_in, const int* in_sizes, int n_in,
                              void* d_out, int out_size) {
    const float* x = (const float*)d_in[0];   // [65536, 256]
    const float* A = (const float*)d_in[1];   // [256, 1024]
    float* out = (float*)d_out;               // [1024, 256, 256]

    cudaFuncSetAttribute(gemm_silu_kernel,
                         cudaFuncAttributeMaxDynamicSharedMemorySize, SMEM_BYTES);

    cvt_A_kernel<<<dim3(32, 8), dim3(32, 8)>>>(A);
    gemm_silu_kernel<<<NCTAS, 256, SMEM_BYTES>>>(x, out);
}

// round 9
// speedup vs baseline: 2.6998x; 2.6998x over previous
#include <cuda_runtime.h>
#include <cuda_bf16.h>
#include <cuda_fp16.h>
#include <cstdint>

// Problem constants (fixed by setup_inputs):
//   x: [65536, 256] f32,  A: [256, 1024] f32
//   out: [1024, 256, 256] f32  (G=1024 blocks of 256x256)
#define B_ROWS  65536
#define DIM     256            // K
#define HDIM    1024           // N total
#define MTILE   128            // rows per CTA
#define NCH     64             // N per chunk
#define NCHUNKS (HDIM / NCH)   // 16
#define NCTAS   (B_ROWS / MTILE) // 512

#define SKP     264                    // fp16 elems per padded SMEM row (528 B; odd 16B stride -> conflict-free)
#define SKPB    (SKP * 2)              // 528 bytes
#define ABYTES  (NCH * SKPB)           // 33792
#define SMEM_BYTES (2 * ABYTES)        // 67584  -> 2 CTAs/SM

// Device scratch: A^T in fp16, [N=1024][K=256] row-major
__device__ __half g_At[HDIM * DIM];

// ---------------- helpers ----------------
__device__ __forceinline__ uint32_t smem_u32(const void* p) {
    uint32_t a;
    asm("{ .reg .u64 t; cvta.to.shared.u64 t, %1; cvt.u32.u64 %0, t; }"
        : "=r"(a) : "l"(p));
    return a;
}

#define LDSM4(r0, r1, r2, r3, addr) \
    asm volatile("ldmatrix.sync.aligned.m8n8.x4.shared.b16 {%0,%1,%2,%3}, [%4];" \
                 : "=r"(r0), "=r"(r1), "=r"(r2), "=r"(r3) : "r"(addr))

// fp16 in / fp16 accumulate: D,C = {2 x b32} (4 halves)
#define MMA16816H(c0, c1, a, b0, b1) \
    asm volatile("mma.sync.aligned.m16n8k16.row.col.f16.f16.f16.f16 " \
                 "{%0,%1}, {%2,%3,%4,%5}, {%6,%7}, {%0,%1};" \
                 : "+r"(c0), "+r"(c1) \
                 : "r"((a)[0]), "r"((a)[1]), "r"((a)[2]), "r"((a)[3]), "r"(b0), "r"(b1))

__device__ __forceinline__ float silu_f(float z) {
    float h = 0.5f * z;
    float t;
    asm("tanh.approx.f32 %0, %1;" : "=f"(t) : "f"(h));
    return fmaf(h, t, h);      // 0.5z + 0.5z*tanh(z/2) = silu(z)
}

__device__ __forceinline__ uint32_t pack_h2(float a, float b) {
    __half2 h = __floats2half2_rn(a, b);
    return *(uint32_t*)&h;
}

__device__ __forceinline__ float2 h2_to_f2(uint32_t u) {
    return __half22float2(*(__half2*)&u);
}

// ---------------- A transpose+convert: A[k][n] f32 -> g_At[n][k] fp16 ----------------
__global__ void cvt_A_kernel(const float* __restrict__ A) {
    __shared__ float tile[32][33];
    int n0 = blockIdx.x * 32;
    int k0 = blockIdx.y * 32;
    int tx = threadIdx.x, ty = threadIdx.y;   // block (32, 8)
#pragma unroll
    for (int r = 0; r < 32; r += 8)
        tile[ty + r][tx] = A[(size_t)(k0 + ty + r) * HDIM + n0 + tx];
    __syncthreads();
#pragma unroll
    for (int r = 0; r < 32; r += 8)
        g_At[(size_t)(n0 + ty + r) * DIM + k0 + tx] = __float2half_rn(tile[tx][ty + r]);
}

// ---------------- fused GEMM(fp16 HMMA) + silu-rowsum + zero-fill + scatter ----------------
__global__ __launch_bounds__(256, 2)
void gemm_silu_kernel(const float* __restrict__ x, float* __restrict__ out) {
    extern __shared__ char smem_raw[];
    __shared__ float red[128];
    const uint32_t sa0 = smem_u32(smem_raw);

    const int tid  = threadIdx.x;
    const int wid  = tid >> 5;        // 8 warps; warp w owns m-rows [16w, 16w+16)
    const int lane = tid & 31;
    const int ct   = blockIdx.x;
    const size_t b0 = (size_t)ct * MTILE;

    // ---- 1) zero-fill this CTA's 512KB output region (2 G-blocks); stores drain in background ----
    {
        float4 z4 = make_float4(0.f, 0.f, 0.f, 0.f);
        float4* zq = (float4*)(out + (size_t)ct * 131072);
#pragma unroll 4
        for (int j = 0; j < 128; j++) zq[tid + j * 256] = z4;
    }

    // ---- 2) prefetch At chunk 0 via cp.async ----
    {
#pragma unroll
        for (int j = 0; j < 8; j++) {
            int idx = tid + j * 256;          // 2048 x 16B
            int nl  = idx >> 5;               // 32 16B-chunks per row
            int kc  = idx & 31;
            uint32_t dst = sa0 + (uint32_t)nl * SKPB + (uint32_t)kc * 16;
            uint64_t src = __cvta_generic_to_global(g_At + (size_t)nl * DIM + kc * 8);
            asm volatile("cp.async.cg.shared.global [%0], [%1], 16;" :: "r"(dst), "l"(src));
        }
        asm volatile("cp.async.commit_group;" ::: "memory");
    }

    // ---- 3) load A-fragments for all K directly from global x (f32 -> fp16 packs), ONCE ----
    uint32_t af[16][4];
    {
        int g = lane >> 2, q = lane & 3;
        const float* xr0 = x + (b0 + (size_t)(wid * 16 + g)) * DIM;   // m_lo row
        const float* xr1 = xr0 + 8 * DIM;                             // m_hi row
#pragma unroll
        for (int kk = 0; kk < 16; kk++) {
            int k0 = kk * 16 + 2 * q;
            float2 v00 = *(const float2*)(xr0 + k0);
            float2 v10 = *(const float2*)(xr1 + k0);
            float2 v01 = *(const float2*)(xr0 + k0 + 8);
            float2 v11 = *(const float2*)(xr1 + k0 + 8);
            af[kk][0] = pack_h2(v00.x, v00.y);
            af[kk][1] = pack_h2(v10.x, v10.y);
            af[kk][2] = pack_h2(v01.x, v01.y);
            af[kk][3] = pack_h2(v11.x, v11.y);
        }
    }

    float rs0 = 0.f, rs1 = 0.f;   // row sums for m = 16w+g and 16w+g+8

    // ---- 4) n-chunk loop: cp.async double-buffered At, MMA + silu-rowsum ----
    const int brow = lane & 7, bmat = lane >> 3;
    for (int c = 0; c < NCHUNKS; c++) {
        if (c + 1 < NCHUNKS) {
            uint32_t sa_n = sa0 + (uint32_t)((c + 1) & 1) * ABYTES;
#pragma unroll
            for (int j = 0; j < 8; j++) {
                int idx = tid + j * 256;
                int nl  = idx >> 5;
                int kc  = idx & 31;
                uint32_t dst = sa_n + (uint32_t)nl * SKPB + (uint32_t)kc * 16;
                uint64_t src = __cvta_generic_to_global(
                    g_At + (size_t)((c + 1) * NCH + nl) * DIM + kc * 8);
                asm volatile("cp.async.cg.shared.global [%0], [%1], 16;" :: "r"(dst), "l"(src));
            }
            asm volatile("cp.async.commit_group;" ::: "memory");
            asm volatile("cp.async.wait_group 1;" ::: "memory");
        } else {
            asm volatile("cp.async.wait_group 0;" ::: "memory");
        }
        __syncthreads();

        const uint32_t sa = sa0 + (uint32_t)(c & 1) * ABYTES;
        const uint32_t bbase = sa + (uint32_t)brow * SKPB + (uint32_t)bmat * 16;

#pragma unroll
        for (int nb = 0; nb < 8; nb++) {
            const uint32_t ba = bbase + (uint32_t)nb * 8 * SKPB;
            uint32_t cA0 = 0u, cA1 = 0u;   // even-kb chain (f16x2 accum)
            uint32_t cB0 = 0u, cB1 = 0u;   // odd-kb chain
            uint32_t bp[2][4];             // double-buffered B frags
            LDSM4(bp[0][0], bp[0][1], bp[0][2], bp[0][3], ba);
#pragma unroll
            for (int kb = 0; kb < 8; kb++) {
                const int cur = kb & 1;
                if (kb < 7) {
                    LDSM4(bp[cur ^ 1][0], bp[cur ^ 1][1], bp[cur ^ 1][2], bp[cur ^ 1][3],
                          ba + (uint32_t)(kb + 1) * 64);
                }
                MMA16816H(cA0, cA1, af[2 * kb],     bp[cur][0], bp[cur][1]);
                MMA16816H(cB0, cB1, af[2 * kb + 1], bp[cur][2], bp[cur][3]);
            }
            // combine chains in f32, apply silu, fold into rowsums
            float2 a0 = h2_to_f2(cA0), b0 = h2_to_f2(cB0);   // row g:   cols 2q, 2q+1
            float2 a1 = h2_to_f2(cA1), b1 = h2_to_f2(cB1);   // row g+8
            rs0 += silu_f(a0.x + b0.x) + silu_f(a0.y + b0.y);
            rs1 += silu_f(a1.x + b1.x) + silu_f(a1.y + b1.y);
        }
        __syncthreads();   // buffer (c&1) may be overwritten by next iteration's prefetch
    }

    // ---- 5) reduce across the 4 threads of each mma group, stage to shared ----
    rs0 += __shfl_xor_sync(0xFFFFFFFFu, rs0, 1);
    rs0 += __shfl_xor_sync(0xFFFFFFFFu, rs0, 2);
    rs1 += __shfl_xor_sync(0xFFFFFFFFu, rs1, 1);
    rs1 += __shfl_xor_sync(0xFFFFFFFFu, rs1, 2);
    if ((lane & 3) == 0) {
        int gid = lane >> 2;
        red[wid * 16 + gid]     = rs0;
        red[wid * 16 + gid + 8] = rs1;
    }
    __syncthreads();

    // ---- 6) scatter +/- s onto the block anti-diagonals (region already zeroed by this CTA) ----
    if (tid < 128) {
        float s = red[tid];
        size_t b = b0 + (size_t)tid;
        size_t g = b >> 6;                 // G block (64 rows per block)
        int i2 = (int)(b & 63) * 2;
        float* og = out + g * 65536;
        og[(size_t)i2 * 256 + 128 + i2]       =  s;   // top-right diag, even
        og[(size_t)(i2 + 1) * 256 + 129 + i2] =  s;   // top-right diag, odd
        og[(size_t)(128 + i2) * 256 + i2]     = -s;   // bottom-left diag, even
        og[(size_t)(129 + i2) * 256 + i2 + 1] = -s;   // bottom-left diag, odd
    }
}

// ---------------- launch ----------------
extern "C" void kernel_launch(void* const* d_in, const int* in_sizes, int n_in,
                              void* d_out, int out_size) {
    const float* x = (const float*)d_in[0];   // [65536, 256]
    const float* A = (const float*)d_in[1];   // [256, 1024]
    float* out = (float*)d_out;               // [1024, 256, 256]

    cudaFuncSetAttribute(gemm_silu_kernel,
                         cudaFuncAttributeMaxDynamicSharedMemorySize, SMEM_BYTES);

    cvt_A_kernel<<<dim3(32, 8), dim3(32, 8)>>>(A);
    gemm_silu_kernel<<<NCTAS, 256, SMEM_BYTES>>>(x, out);
}

// round 10
// speedup vs baseline: 2.9003x; 1.0743x over previous
#include <cuda_runtime.h>
#include <cuda_bf16.h>
#include <cuda_fp16.h>
#include <cstdint>

// Problem constants (fixed by setup_inputs):
//   x: [65536, 256] f32,  A: [256, 1024] f32
//   out: [1024, 256, 256] f32  (G=1024 blocks of 256x256)
#define B_ROWS  65536
#define DIM     256            // K
#define HDIM    1024           // N total
#define MTILE   128            // rows per CTA
#define NCH     64             // N per chunk
#define NCHUNKS (HDIM / NCH)   // 16
#define NCTAS   (B_ROWS / MTILE) // 512

#define SKP     264                    // fp16 elems per padded SMEM row (528 B; odd 16B stride -> conflict-free)
#define SKPB    (SKP * 2)              // 528 bytes
#define ABYTES  (NCH * SKPB)           // 33792
#define SMEM_BYTES (2 * ABYTES)        // 67584  -> 2 CTAs/SM

// Device scratch: A^T in fp16, [N=1024][K=256] row-major
__device__ __half g_At[HDIM * DIM];

// ---------------- helpers ----------------
__device__ __forceinline__ uint32_t smem_u32(const void* p) {
    uint32_t a;
    asm("{ .reg .u64 t; cvta.to.shared.u64 t, %1; cvt.u32.u64 %0, t; }"
        : "=r"(a) : "l"(p));
    return a;
}

#define LDSM4(r0, r1, r2, r3, addr) \
    asm volatile("ldmatrix.sync.aligned.m8n8.x4.shared.b16 {%0,%1,%2,%3}, [%4];" \
                 : "=r"(r0), "=r"(r1), "=r"(r2), "=r"(r3) : "r"(addr))

// fp16 in / fp16 accumulate: D,C = {2 x b32} (4 halves)
#define MMA16816H(c0, c1, a, b0, b1) \
    asm volatile("mma.sync.aligned.m16n8k16.row.col.f16.f16.f16.f16 " \
                 "{%0,%1}, {%2,%3,%4,%5}, {%6,%7}, {%0,%1};" \
                 : "+r"(c0), "+r"(c1) \
                 : "r"((a)[0]), "r"((a)[1]), "r"((a)[2]), "r"((a)[3]), "r"(b0), "r"(b1))

__device__ __forceinline__ float silu_f(float z) {
    float h = 0.5f * z;
    float t;
    asm("tanh.approx.f32 %0, %1;" : "=f"(t) : "f"(h));
    return fmaf(h, t, h);      // 0.5z + 0.5z*tanh(z/2) = silu(z)
}

__device__ __forceinline__ uint32_t pack_h2(float a, float b) {
    __half2 h = __floats2half2_rn(a, b);
    return *(uint32_t*)&h;
}

__device__ __forceinline__ float2 h2_to_f2(uint32_t u) {
    return __half22float2(*(__half2*)&u);
}

// streaming (evict-first) 16B zero store
__device__ __forceinline__ void stg_cs_zero16(float4* p) {
    asm volatile("st.global.cs.v4.f32 [%0], {%1,%1,%1,%1};"
                 :: "l"(p), "f"(0.0f) : "memory");
}

// ---------------- A transpose+convert: A[k][n] f32 -> g_At[n][k] fp16 ----------------
__global__ void cvt_A_kernel(const float* __restrict__ A) {
    __shared__ float tile[32][33];
    int n0 = blockIdx.x * 32;
    int k0 = blockIdx.y * 32;
    int tx = threadIdx.x, ty = threadIdx.y;   // block (32, 8)
#pragma unroll
    for (int r = 0; r < 32; r += 8)
        tile[ty + r][tx] = A[(size_t)(k0 + ty + r) * HDIM + n0 + tx];
    __syncthreads();
#pragma unroll
    for (int r = 0; r < 32; r += 8)
        g_At[(size_t)(n0 + ty + r) * DIM + k0 + tx] = __float2half_rn(tile[tx][ty + r]);
}

// ---------------- fused GEMM(fp16 HMMA) + silu-rowsum + zero-fill + scatter ----------------
__global__ __launch_bounds__(256, 2)
void gemm_silu_kernel(const float* __restrict__ x, float* __restrict__ out) {
    extern __shared__ char smem_raw[];
    __shared__ float red[128];
    const uint32_t sa0 = smem_u32(smem_raw);

    const int tid  = threadIdx.x;
    const int wid  = tid >> 5;        // 8 warps; warp w owns m-rows [16w, 16w+16)
    const int lane = tid & 31;
    const int ct   = blockIdx.x;
    const size_t b0 = (size_t)ct * MTILE;

    // ---- 1) prefetch At chunk 0 via cp.async ----
    {
#pragma unroll
        for (int j = 0; j < 8; j++) {
            int idx = tid + j * 256;          // 2048 x 16B
            int nl  = idx >> 5;               // 32 16B-chunks per row
            int kc  = idx & 31;
            uint32_t dst = sa0 + (uint32_t)nl * SKPB + (uint32_t)kc * 16;
            uint64_t src = __cvta_generic_to_global(g_At + (size_t)nl * DIM + kc * 8);
            asm volatile("cp.async.cg.shared.global [%0], [%1], 16;" :: "r"(dst), "l"(src));
        }
        asm volatile("cp.async.commit_group;" ::: "memory");
    }

    // ---- 2) load A-fragments for all K directly from global x (f32 -> fp16 packs), ONCE ----
    uint32_t af[16][4];
    {
        int g = lane >> 2, q = lane & 3;
        const float* xr0 = x + (b0 + (size_t)(wid * 16 + g)) * DIM;   // m_lo row
        const float* xr1 = xr0 + 8 * DIM;                             // m_hi row
#pragma unroll
        for (int kk = 0; kk < 16; kk++) {
            int k0 = kk * 16 + 2 * q;
            float2 v00 = *(const float2*)(xr0 + k0);
            float2 v10 = *(const float2*)(xr1 + k0);
            float2 v01 = *(const float2*)(xr0 + k0 + 8);
            float2 v11 = *(const float2*)(xr1 + k0 + 8);
            af[kk][0] = pack_h2(v00.x, v00.y);
            af[kk][1] = pack_h2(v10.x, v10.y);
            af[kk][2] = pack_h2(v01.x, v01.y);
            af[kk][3] = pack_h2(v11.x, v11.y);
        }
    }

    float rs0 = 0.f, rs1 = 0.f;   // row sums for m = 16w+g and 16w+g+8
    float4* zball = (float4*)(out + (size_t)ct * 131072);  // this CTA's 512KB region

    // ---- 3) n-chunk loop: cp.async double-buffered At, interleaved zero-fill, MMA + silu ----
    const int brow = lane & 7, bmat = lane >> 3;
    for (int c = 0; c < NCHUNKS; c++) {
        if (c + 1 < NCHUNKS) {
            uint32_t sa_n = sa0 + (uint32_t)((c + 1) & 1) * ABYTES;
#pragma unroll
            for (int j = 0; j < 8; j++) {
                int idx = tid + j * 256;
                int nl  = idx >> 5;
                int kc  = idx & 31;
                uint32_t dst = sa_n + (uint32_t)nl * SKPB + (uint32_t)kc * 16;
                uint64_t src = __cvta_generic_to_global(
                    g_At + (size_t)((c + 1) * NCH + nl) * DIM + kc * 8);
                asm volatile("cp.async.cg.shared.global [%0], [%1], 16;" :: "r"(dst), "l"(src));
            }
            asm volatile("cp.async.commit_group;" ::: "memory");
        }

        // interleaved zero-fill: 1/16 of this CTA's output region (32KB, streaming stores)
        {
            float4* zq = zball + (size_t)c * 2048;
#pragma unroll
            for (int j = 0; j < 8; j++) stg_cs_zero16(zq + tid + j * 256);
        }

        if (c + 1 < NCHUNKS) {
            asm volatile("cp.async.wait_group 1;" ::: "memory");
        } else {
            asm volatile("cp.async.wait_group 0;" ::: "memory");
        }
        __syncthreads();

        const uint32_t sa = sa0 + (uint32_t)(c & 1) * ABYTES;
        const uint32_t bbase = sa + (uint32_t)brow * SKPB + (uint32_t)bmat * 16;

#pragma unroll
        for (int nb = 0; nb < 8; nb++) {
            const uint32_t ba = bbase + (uint32_t)nb * 8 * SKPB;
            uint32_t cA0 = 0u, cA1 = 0u;   // even-kb chain (f16x2 accum)
            uint32_t cB0 = 0u, cB1 = 0u;   // odd-kb chain
            uint32_t bp[2][4];             // double-buffered B frags
            LDSM4(bp[0][0], bp[0][1], bp[0][2], bp[0][3], ba);
#pragma unroll
            for (int kb = 0; kb < 8; kb++) {
                const int cur = kb & 1;
                if (kb < 7) {
                    LDSM4(bp[cur ^ 1][0], bp[cur ^ 1][1], bp[cur ^ 1][2], bp[cur ^ 1][3],
                          ba + (uint32_t)(kb + 1) * 64);
                }
                MMA16816H(cA0, cA1, af[2 * kb],     bp[cur][0], bp[cur][1]);
                MMA16816H(cB0, cB1, af[2 * kb + 1], bp[cur][2], bp[cur][3]);
            }
            // combine chains in f32, apply silu, fold into rowsums
            float2 a0 = h2_to_f2(cA0), b0 = h2_to_f2(cB0);   // row g:   cols 2q, 2q+1
            float2 a1 = h2_to_f2(cA1), b1 = h2_to_f2(cB1);   // row g+8
            rs0 += silu_f(a0.x + b0.x) + silu_f(a0.y + b0.y);
            rs1 += silu_f(a1.x + b1.x) + silu_f(a1.y + b1.y);
        }
        __syncthreads();   // buffer (c&1) may be overwritten by next iteration's prefetch
    }

    // ---- 4) reduce across the 4 threads of each mma group, stage to shared ----
    rs0 += __shfl_xor_sync(0xFFFFFFFFu, rs0, 1);
    rs0 += __shfl_xor_sync(0xFFFFFFFFu, rs0, 2);
    rs1 += __shfl_xor_sync(0xFFFFFFFFu, rs1, 1);
    rs1 += __shfl_xor_sync(0xFFFFFFFFu, rs1, 2);
    if ((lane & 3) == 0) {
        int gid = lane >> 2;
        red[wid * 16 + gid]     = rs0;
        red[wid * 16 + gid + 8] = rs1;
    }
    __syncthreads();

    // ---- 5) scatter +/- s onto the block anti-diagonals (region already zeroed by this CTA) ----
    if (tid < 128) {
        float s = red[tid];
        size_t b = b0 + (size_t)tid;
        size_t g = b >> 6;                 // G block (64 rows per block)
        int i2 = (int)(b & 63) * 2;
        float* og = out + g * 65536;
        og[(size_t)i2 * 256 + 128 + i2]       =  s;   // top-right diag, even
        og[(size_t)(i2 + 1) * 256 + 129 + i2] =  s;   // top-right diag, odd
        og[(size_t)(128 + i2) * 256 + i2]     = -s;   // bottom-left diag, even
        og[(size_t)(129 + i2) * 256 + i2 + 1] = -s;   // bottom-left diag, odd
    }
}

// ---------------- launch ----------------
extern "C" void kernel_launch(void* const* d_in, const int* in_sizes, int n_in,
                              void* d_out, int out_size) {
    const float* x = (const float*)d_in[0];   // [65536, 256]
    const float* A = (const float*)d_in[1];   // [256, 1024]
    float* out = (float*)d_out;               // [1024, 256, 256]

    cudaFuncSetAttribute(gemm_silu_kernel,
                         cudaFuncAttributeMaxDynamicSharedMemorySize, SMEM_BYTES);

    cvt_A_kernel<<<dim3(32, 8), dim3(32, 8)>>>(A);
    gemm_silu_kernel<<<NCTAS, 256, SMEM_BYTES>>>(x, out);
}

// round 11
// speedup vs baseline: 2.9297x; 1.0101x over previous
#include <cuda_runtime.h>
#include <cuda_bf16.h>
#include <cuda_fp16.h>
#include <cstdint>

// Problem constants (fixed by setup_inputs):
//   x: [65536, 256] f32,  A: [256, 1024] f32
//   out: [1024, 256, 256] f32  (G=1024 blocks of 256x256)
#define B_ROWS  65536
#define DIM     256            // K
#define HDIM    1024           // N total
#define MTILE   128            // rows per CTA
#define NCH     64             // N per chunk
#define NCHUNKS (HDIM / NCH)   // 16
#define NCTAS   (B_ROWS / MTILE) // 512

#define SKP     264                    // fp16 elems per padded SMEM row (528 B; odd 16B stride -> conflict-free)
#define SKPB    (SKP * 2)              // 528 bytes
#define ABYTES  (NCH * SKPB)           // 33792
#define SMEM_BYTES (2 * ABYTES)        // 67584  -> 2 CTAs/SM

// Device scratch: A^T in fp16, [N=1024][K=256] row-major
__device__ __half g_At[HDIM * DIM];

// ---------------- helpers ----------------
__device__ __forceinline__ uint32_t smem_u32(const void* p) {
    uint32_t a;
    asm("{ .reg .u64 t; cvta.to.shared.u64 t, %1; cvt.u32.u64 %0, t; }"
        : "=r"(a) : "l"(p));
    return a;
}

#define LDSM4(r0, r1, r2, r3, addr) \
    asm volatile("ldmatrix.sync.aligned.m8n8.x4.shared.b16 {%0,%1,%2,%3}, [%4];" \
                 : "=r"(r0), "=r"(r1), "=r"(r2), "=r"(r3) : "r"(addr))

// fp16 in / fp16 accumulate: D,C = {2 x b32} (4 halves)
#define MMA16816H(c0, c1, a, b0, b1) \
    asm volatile("mma.sync.aligned.m16n8k16.row.col.f16.f16.f16.f16 " \
                 "{%0,%1}, {%2,%3,%4,%5}, {%6,%7}, {%0,%1};" \
                 : "+r"(c0), "+r"(c1) \
                 : "r"((a)[0]), "r"((a)[1]), "r"((a)[2]), "r"((a)[3]), "r"(b0), "r"(b1))

__device__ __forceinline__ float silu_f(float z) {
    float h = 0.5f * z;
    float t;
    asm("tanh.approx.f32 %0, %1;" : "=f"(t) : "f"(h));
    return fmaf(h, t, h);      // 0.5z + 0.5z*tanh(z/2) = silu(z)
}

__device__ __forceinline__ uint32_t pack_h2(float a, float b) {
    __half2 h = __floats2half2_rn(a, b);
    return *(uint32_t*)&h;
}

__device__ __forceinline__ float2 h2_to_f2(uint32_t u) {
    return __half22float2(*(__half2*)&u);
}

// streaming (evict-first) 16B zero store
__device__ __forceinline__ void stg_cs_zero16(float4* p) {
    asm volatile("st.global.cs.v4.f32 [%0], {%1,%1,%1,%1};"
                 :: "l"(p), "f"(0.0f) : "memory");
}

// ---------------- A transpose+convert: A[k][n] f32 -> g_At[n][k] fp16 ----------------
__global__ void cvt_A_kernel(const float* __restrict__ A) {
    __shared__ float tile[32][33];
    int n0 = blockIdx.x * 32;
    int k0 = blockIdx.y * 32;
    int tx = threadIdx.x, ty = threadIdx.y;   // block (32, 8)
#pragma unroll
    for (int r = 0; r < 32; r += 8)
        tile[ty + r][tx] = A[(size_t)(k0 + ty + r) * HDIM + n0 + tx];
    __syncthreads();
#pragma unroll
    for (int r = 0; r < 32; r += 8)
        g_At[(size_t)(n0 + ty + r) * DIM + k0 + tx] = __float2half_rn(tile[tx][ty + r]);
}

// ---------------- fused GEMM(fp16 HMMA) + silu-rowsum + zero-fill + scatter ----------------
__global__ __launch_bounds__(256, 2)
void gemm_silu_kernel(const float* __restrict__ x, float* __restrict__ out) {
    extern __shared__ char smem_raw[];
    __shared__ float red[128];
    const uint32_t sa0 = smem_u32(smem_raw);

    const int tid  = threadIdx.x;
    const int wid  = tid >> 5;        // 8 warps; warp w owns m-rows [16w, 16w+16)
    const int lane = tid & 31;
    const int ct   = blockIdx.x;
    const size_t b0 = (size_t)ct * MTILE;

    // ---- 1) prefetch At chunk 0 via cp.async ----
    {
#pragma unroll
        for (int j = 0; j < 8; j++) {
            int idx = tid + j * 256;          // 2048 x 16B
            int nl  = idx >> 5;               // 32 16B-chunks per row
            int kc  = idx & 31;
            uint32_t dst = sa0 + (uint32_t)nl * SKPB + (uint32_t)kc * 16;
            uint64_t src = __cvta_generic_to_global(g_At + (size_t)nl * DIM + kc * 8);
            asm volatile("cp.async.cg.shared.global [%0], [%1], 16;" :: "r"(dst), "l"(src));
        }
        asm volatile("cp.async.commit_group;" ::: "memory");
    }

    // ---- 2) load A-fragments for all K directly from global x (f32 -> fp16 packs), ONCE ----
    uint32_t af[16][4];
    {
        int g = lane >> 2, q = lane & 3;
        const float* xr0 = x + (b0 + (size_t)(wid * 16 + g)) * DIM;   // m_lo row
        const float* xr1 = xr0 + 8 * DIM;                             // m_hi row
#pragma unroll
        for (int kk = 0; kk < 16; kk++) {
            int k0 = kk * 16 + 2 * q;
            float2 v00 = *(const float2*)(xr0 + k0);
            float2 v10 = *(const float2*)(xr1 + k0);
            float2 v01 = *(const float2*)(xr0 + k0 + 8);
            float2 v11 = *(const float2*)(xr1 + k0 + 8);
            af[kk][0] = pack_h2(v00.x, v00.y);
            af[kk][1] = pack_h2(v10.x, v10.y);
            af[kk][2] = pack_h2(v01.x, v01.y);
            af[kk][3] = pack_h2(v11.x, v11.y);
        }
    }

    float rs0 = 0.f, rs1 = 0.f;   // row sums for m = 16w+g and 16w+g+8
    float4* zball = (float4*)(out + (size_t)ct * 131072);  // this CTA's 512KB region

    // ---- 3) n-chunk loop: cp.async double-buffered At, interleaved zero-fill,
    //         stage-pipelined LDSM/MMA, silu-rowsum ----
    const int brow = lane & 7, bmat = lane >> 3;
    for (int c = 0; c < NCHUNKS; c++) {
        if (c + 1 < NCHUNKS) {
            uint32_t sa_n = sa0 + (uint32_t)((c + 1) & 1) * ABYTES;
#pragma unroll
            for (int j = 0; j < 8; j++) {
                int idx = tid + j * 256;
                int nl  = idx >> 5;
                int kc  = idx & 31;
                uint32_t dst = sa_n + (uint32_t)nl * SKPB + (uint32_t)kc * 16;
                uint64_t src = __cvta_generic_to_global(
                    g_At + (size_t)((c + 1) * NCH + nl) * DIM + kc * 8);
                asm volatile("cp.async.cg.shared.global [%0], [%1], 16;" :: "r"(dst), "l"(src));
            }
            asm volatile("cp.async.commit_group;" ::: "memory");
        }

        // interleaved zero-fill: 1/16 of this CTA's output region (32KB, streaming stores)
        {
            float4* zq = zball + (size_t)c * 2048;
#pragma unroll
            for (int j = 0; j < 8; j++) stg_cs_zero16(zq + tid + j * 256);
        }

        if (c + 1 < NCHUNKS) {
            asm volatile("cp.async.wait_group 1;" ::: "memory");
        } else {
            asm volatile("cp.async.wait_group 0;" ::: "memory");
        }
        __syncthreads();

        const uint32_t sa = sa0 + (uint32_t)(c & 1) * ABYTES;
        const uint32_t bbase = sa + (uint32_t)brow * SKPB + (uint32_t)bmat * 16;

        // 16 stages: stage s covers nb = s>>1, k-half h = s&1 (4 kb's, 8 MMAs).
        // B frags double-buffered at stage level: stage s consumes bb[s&1],
        // prefetches stage s+1 into bb[(s&1)^1] BEFORE its MMAs -> LDSM-use
        // distance ~ 8 MMA + 4 LDSM instrs (>= 64-100 cyc of issue).
        uint32_t bb[2][4][4];
        uint32_t cA0 = 0u, cA1 = 0u, cB0 = 0u, cB1 = 0u;
        // preload stage 0 (nb=0, h=0): addr = bbase + i*64
        LDSM4(bb[0][0][0], bb[0][0][1], bb[0][0][2], bb[0][0][3], bbase);
        LDSM4(bb[0][1][0], bb[0][1][1], bb[0][1][2], bb[0][1][3], bbase + 64u);
        LDSM4(bb[0][2][0], bb[0][2][1], bb[0][2][2], bb[0][2][3], bbase + 128u);
        LDSM4(bb[0][3][0], bb[0][3][1], bb[0][3][2], bb[0][3][3], bbase + 192u);
#pragma unroll
        for (int s = 0; s < 16; s++) {
            const int buf = s & 1;
            const int h   = s & 1;        // k-half within nb
            if (s + 1 < 16) {
                const int nb1 = (s + 1) >> 1, h1 = (s + 1) & 1;
                const uint32_t a1 = bbase + (uint32_t)nb1 * 8u * SKPB
                                  + (uint32_t)(h1 * 4) * 64u;
#pragma unroll
                for (int i = 0; i < 4; i++) {
                    LDSM4(bb[buf ^ 1][i][0], bb[buf ^ 1][i][1],
                          bb[buf ^ 1][i][2], bb[buf ^ 1][i][3], a1 + (uint32_t)i * 64u);
                }
            }
#pragma unroll
            for (int i = 0; i < 4; i++) {
                const int kb = h * 4 + i;
                MMA16816H(cA0, cA1, af[2 * kb],     bb[buf][i][0], bb[buf][i][1]);
                MMA16816H(cB0, cB1, af[2 * kb + 1], bb[buf][i][2], bb[buf][i][3]);
            }
            if (h == 1) {
                // nb complete: combine chains in f32, silu, fold into rowsums
                float2 a0 = h2_to_f2(cA0), b0f = h2_to_f2(cB0);   // row g
                float2 a1 = h2_to_f2(cA1), b1f = h2_to_f2(cB1);   // row g+8
                rs0 += silu_f(a0.x + b0f.x) + silu_f(a0.y + b0f.y);
                rs1 += silu_f(a1.x + b1f.x) + silu_f(a1.y + b1f.y);
                cA0 = 0u; cA1 = 0u; cB0 = 0u; cB1 = 0u;
            }
        }
        __syncthreads();   // buffer (c&1) may be overwritten by next iteration's prefetch
    }

    // ---- 4) reduce across the 4 threads of each mma group, stage to shared ----
    rs0 += __shfl_xor_sync(0xFFFFFFFFu, rs0, 1);
    rs0 += __shfl_xor_sync(0xFFFFFFFFu, rs0, 2);
    rs1 += __shfl_xor_sync(0xFFFFFFFFu, rs1, 1);
    rs1 += __shfl_xor_sync(0xFFFFFFFFu, rs1, 2);
    if ((lane & 3) == 0) {
        int gid = lane >> 2;
        red[wid * 16 + gid]     = rs0;
        red[wid * 16 + gid + 8] = rs1;
    }
    __syncthreads();

    // ---- 5) scatter +/- s onto the block anti-diagonals (region already zeroed by this CTA) ----
    if (tid < 128) {
        float s = red[tid];
        size_t b = b0 + (size_t)tid;
        size_t g = b >> 6;                 // G block (64 rows per block)
        int i2 = (int)(b & 63) * 2;
        float* og = out + g * 65536;
        og[(size_t)i2 * 256 + 128 + i2]       =  s;   // top-right diag, even
        og[(size_t)(i2 + 1) * 256 + 129 + i2] =  s;   // top-right diag, odd
        og[(size_t)(128 + i2) * 256 + i2]     = -s;   // bottom-left diag, even
        og[(size_t)(129 + i2) * 256 + i2 + 1] = -s;   // bottom-left diag, odd
    }
}

// ---------------- launch ----------------
extern "C" void kernel_launch(void* const* d_in, const int* in_sizes, int n_in,
                              void* d_out, int out_size) {
    const float* x = (const float*)d_in[0];   // [65536, 256]
    const float* A = (const float*)d_in[1];   // [256, 1024]
    float* out = (float*)d_out;               // [1024, 256, 256]

    cudaFuncSetAttribute(gemm_silu_kernel,
                         cudaFuncAttributeMaxDynamicSharedMemorySize, SMEM_BYTES);

    cvt_A_kernel<<<dim3(32, 8), dim3(32, 8)>>>(A);
    gemm_silu_kernel<<<NCTAS, 256, SMEM_BYTES>>>(x, out);
}

// round 12
// speedup vs baseline: 2.9861x; 1.0193x over previous
#include <cuda_runtime.h>
#include <cuda_bf16.h>
#include <cuda_fp16.h>
#include <cstdint>

// Problem constants (fixed by setup_inputs):
//   x: [65536, 256] f32,  A: [256, 1024] f32
//   out: [1024, 256, 256] f32  (G=1024 blocks of 256x256)
#define B_ROWS  65536
#define DIM     256            // K
#define HDIM    1024           // N total
#define MTILE   128            // rows per CTA
#define NCH     64             // N per chunk
#define NCHUNKS (HDIM / NCH)   // 16
#define NCTAS   (B_ROWS / MTILE) // 512

#define SKP     264                    // fp16 elems per padded SMEM row (528 B; odd 16B stride -> conflict-free)
#define SKPB    (SKP * 2)              // 528 bytes
#define ABYTES  (NCH * SKPB)           // 33792
#define SMEM_BYTES (2 * ABYTES)        // 67584  -> 2 CTAs/SM

// Device scratch: A^T in fp16, [N=1024][K=256] row-major
__device__ __half g_At[HDIM * DIM];

// ---------------- helpers ----------------
__device__ __forceinline__ uint32_t smem_u32(const void* p) {
    uint32_t a;
    asm("{ .reg .u64 t; cvta.to.shared.u64 t, %1; cvt.u32.u64 %0, t; }"
        : "=r"(a) : "l"(p));
    return a;
}

#define LDSM4(r0, r1, r2, r3, addr) \
    asm volatile("ldmatrix.sync.aligned.m8n8.x4.shared.b16 {%0,%1,%2,%3}, [%4];" \
                 : "=r"(r0), "=r"(r1), "=r"(r2), "=r"(r3) : "r"(addr))

// fp16 in / fp16 accumulate: D,C = {2 x b32} (4 halves)
#define MMA16816H(c0, c1, a, b0, b1) \
    asm volatile("mma.sync.aligned.m16n8k16.row.col.f16.f16.f16.f16 " \
                 "{%0,%1}, {%2,%3,%4,%5}, {%6,%7}, {%0,%1};" \
                 : "+r"(c0), "+r"(c1) \
                 : "r"((a)[0]), "r"((a)[1]), "r"((a)[2]), "r"((a)[3]), "r"(b0), "r"(b1))

__device__ __forceinline__ float silu_f(float z) {
    float h = 0.5f * z;
    float t;
    asm("tanh.approx.f32 %0, %1;" : "=f"(t) : "f"(h));
    return fmaf(h, t, h);      // 0.5z + 0.5z*tanh(z/2) = silu(z)
}

__device__ __forceinline__ uint32_t pack_h2(float a, float b) {
    __half2 h = __floats2half2_rn(a, b);
    return *(uint32_t*)&h;
}

__device__ __forceinline__ float2 h2_to_f2(uint32_t u) {
    return __half22float2(*(__half2*)&u);
}

// streaming (evict-first) 16B zero store
__device__ __forceinline__ void stg_cs_zero16(float4* p) {
    asm volatile("st.global.cs.v4.f32 [%0], {%1,%1,%1,%1};"
                 :: "l"(p), "f"(0.0f) : "memory");
}

// ---------------- A transpose+convert: A[k][n] f32 -> g_At[n][k] fp16 ----------------
__global__ void cvt_A_kernel(const float* __restrict__ A) {
    __shared__ float tile[32][33];
    int n0 = blockIdx.x * 32;
    int k0 = blockIdx.y * 32;
    int tx = threadIdx.x, ty = threadIdx.y;   // block (32, 8)
#pragma unroll
    for (int r = 0; r < 32; r += 8)
        tile[ty + r][tx] = A[(size_t)(k0 + ty + r) * HDIM + n0 + tx];
    __syncthreads();
#pragma unroll
    for (int r = 0; r < 32; r += 8)
        g_At[(size_t)(n0 + ty + r) * DIM + k0 + tx] = __float2half_rn(tile[tx][ty + r]);
}

// ---------------- fused GEMM(fp16 HMMA) + silu-rowsum + zero-fill + scatter ----------------
__global__ __launch_bounds__(256, 2)
void gemm_silu_kernel(const float* __restrict__ x, float* __restrict__ out) {
    extern __shared__ char smem_raw[];
    __shared__ float red[128];
    const uint32_t sa0 = smem_u32(smem_raw);

    const int tid  = threadIdx.x;
    const int wid  = tid >> 5;        // 8 warps; warp w owns m-rows [16w, 16w+16)
    const int lane = tid & 31;
    const int ct   = blockIdx.x;
    const size_t b0 = (size_t)ct * MTILE;

    // ---- 1) prefetch At chunk 0 via cp.async ----
    {
#pragma unroll
        for (int j = 0; j < 8; j++) {
            int idx = tid + j * 256;          // 2048 x 16B
            int nl  = idx >> 5;               // 32 16B-chunks per row
            int kc  = idx & 31;
            uint32_t dst = sa0 + (uint32_t)nl * SKPB + (uint32_t)kc * 16;
            uint64_t src = __cvta_generic_to_global(g_At + (size_t)nl * DIM + kc * 8);
            asm volatile("cp.async.cg.shared.global [%0], [%1], 16;" :: "r"(dst), "l"(src));
        }
        asm volatile("cp.async.commit_group;" ::: "memory");
    }

    // ---- 2) load A-fragments for all K directly from global x (f32 -> fp16 packs), ONCE ----
    uint32_t af[16][4];
    {
        int g = lane >> 2, q = lane & 3;
        const float* xr0 = x + (b0 + (size_t)(wid * 16 + g)) * DIM;   // m_lo row
        const float* xr1 = xr0 + 8 * DIM;                             // m_hi row
#pragma unroll
        for (int kk = 0; kk < 16; kk++) {
            int k0 = kk * 16 + 2 * q;
            float2 v00 = *(const float2*)(xr0 + k0);
            float2 v10 = *(const float2*)(xr1 + k0);
            float2 v01 = *(const float2*)(xr0 + k0 + 8);
            float2 v11 = *(const float2*)(xr1 + k0 + 8);
            af[kk][0] = pack_h2(v00.x, v00.y);
            af[kk][1] = pack_h2(v10.x, v10.y);
            af[kk][2] = pack_h2(v01.x, v01.y);
            af[kk][3] = pack_h2(v11.x, v11.y);
        }
    }

    float rs0 = 0.f, rs1 = 0.f;   // row sums for m = 16w+g and 16w+g+8
    float4* zball = (float4*)(out + (size_t)ct * 131072);  // this CTA's 512KB region

    // ---- 3) n-chunk loop ----
    const int brow = lane & 7, bmat = lane >> 3;
    for (int c = 0; c < NCHUNKS; c++) {
        if (c + 1 < NCHUNKS) {
            uint32_t sa_n = sa0 + (uint32_t)((c + 1) & 1) * ABYTES;
#pragma unroll
            for (int j = 0; j < 8; j++) {
                int idx = tid + j * 256;
                int nl  = idx >> 5;
                int kc  = idx & 31;
                uint32_t dst = sa_n + (uint32_t)nl * SKPB + (uint32_t)kc * 16;
                uint64_t src = __cvta_generic_to_global(
                    g_At + (size_t)((c + 1) * NCH + nl) * DIM + kc * 8);
                asm volatile("cp.async.cg.shared.global [%0], [%1], 16;" :: "r"(dst), "l"(src));
            }
            asm volatile("cp.async.commit_group;" ::: "memory");
        }

        // interleaved zero-fill: 1/16 of this CTA's output region (32KB, streaming stores)
        {
            float4* zq = zball + (size_t)c * 2048;
#pragma unroll
            for (int j = 0; j < 8; j++) stg_cs_zero16(zq + tid + j * 256);
        }

        if (c + 1 < NCHUNKS) {
            asm volatile("cp.async.wait_group 1;" ::: "memory");
        } else {
            asm volatile("cp.async.wait_group 0;" ::: "memory");
        }
        __syncthreads();

        const uint32_t sa = sa0 + (uint32_t)(c & 1) * ABYTES;
        const uint32_t bbase = sa + (uint32_t)brow * SKPB + (uint32_t)bmat * 16;

        // Two nb-groups of 4 n8-blocks. Per group: 8 j-steps (k16 pairs);
        // each j: [4 LDSM batched for next j] then TWO runs of 4 consecutive
        // MMAs sharing one A fragment (af[2j], then af[2j+1]) -> tests the
        // A-operand-reuse dispatch fast path.
#pragma unroll
        for (int g2 = 0; g2 < 2; g2++) {
            uint32_t d0[4], d1[4];            // fp16x2 accumulators per nb
#pragma unroll
            for (int nb = 0; nb < 4; nb++) { d0[nb] = 0u; d1[nb] = 0u; }

            uint32_t bq[2][4][4];             // [buf][nb][reg], double-buffered per j
            const uint32_t gb = bbase + (uint32_t)(g2 * 4) * 8u * SKPB;
#pragma unroll
            for (int nb = 0; nb < 4; nb++) {  // preload j=0
                const uint32_t ba = gb + (uint32_t)nb * 8u * SKPB;
                LDSM4(bq[0][nb][0], bq[0][nb][1], bq[0][nb][2], bq[0][nb][3], ba);
            }
#pragma unroll
            for (int j = 0; j < 8; j++) {
                const int cur = j & 1;
                if (j < 7) {
#pragma unroll
                    for (int nb = 0; nb < 4; nb++) {
                        const uint32_t ba = gb + (uint32_t)nb * 8u * SKPB
                                          + (uint32_t)(j + 1) * 64u;
                        LDSM4(bq[cur ^ 1][nb][0], bq[cur ^ 1][nb][1],
                              bq[cur ^ 1][nb][2], bq[cur ^ 1][nb][3], ba);
                    }
                }
                // run 1: 4 consecutive MMAs sharing af[2j]
#pragma unroll
                for (int nb = 0; nb < 4; nb++)
                    MMA16816H(d0[nb], d1[nb], af[2 * j], bq[cur][nb][0], bq[cur][nb][1]);
                // run 2: 4 consecutive MMAs sharing af[2j+1]
#pragma unroll
                for (int nb = 0; nb < 4; nb++)
                    MMA16816H(d0[nb], d1[nb], af[2 * j + 1], bq[cur][nb][2], bq[cur][nb][3]);
            }
#pragma unroll
            for (int nb = 0; nb < 4; nb++) {
                float2 a0 = h2_to_f2(d0[nb]);   // row g:   cols 2q, 2q+1
                float2 a1 = h2_to_f2(d1[nb]);   // row g+8
                rs0 += silu_f(a0.x) + silu_f(a0.y);
                rs1 += silu_f(a1.x) + silu_f(a1.y);
            }
        }
        __syncthreads();   // buffer (c&1) may be overwritten by next iteration's prefetch
    }

    // ---- 4) reduce across the 4 threads of each mma group, stage to shared ----
    rs0 += __shfl_xor_sync(0xFFFFFFFFu, rs0, 1);
    rs0 += __shfl_xor_sync(0xFFFFFFFFu, rs0, 2);
    rs1 += __shfl_xor_sync(0xFFFFFFFFu, rs1, 1);
    rs1 += __shfl_xor_sync(0xFFFFFFFFu, rs1, 2);
    if ((lane & 3) == 0) {
        int gid = lane >> 2;
        red[wid * 16 + gid]     = rs0;
        red[wid * 16 + gid + 8] = rs1;
    }
    __syncthreads();

    // ---- 5) scatter +/- s onto the block anti-diagonals (region already zeroed by this CTA) ----
    if (tid < 128) {
        float s = red[tid];
        size_t b = b0 + (size_t)tid;
        size_t g = b >> 6;                 // G block (64 rows per block)
        int i2 = (int)(b & 63) * 2;
        float* og = out + g * 65536;
        og[(size_t)i2 * 256 + 128 + i2]       =  s;   // top-right diag, even
        og[(size_t)(i2 + 1) * 256 + 129 + i2] =  s;   // top-right diag, odd
        og[(size_t)(128 + i2) * 256 + i2]     = -s;   // bottom-left diag, even
        og[(size_t)(129 + i2) * 256 + i2 + 1] = -s;   // bottom-left diag, odd
    }
}

// ---------------- launch ----------------
extern "C" void kernel_launch(void* const* d_in, const int* in_sizes, int n_in,
                              void* d_out, int out_size) {
    const float* x = (const float*)d_in[0];   // [65536, 256]
    const float* A = (const float*)d_in[1];   // [256, 1024]
    float* out = (float*)d_out;               // [1024, 256, 256]

    cudaFuncSetAttribute(gemm_silu_kernel,
                         cudaFuncAttributeMaxDynamicSharedMemorySize, SMEM_BYTES);

    cvt_A_kernel<<<dim3(32, 8), dim3(32, 8)>>>(A);
    gemm_silu_kernel<<<NCTAS, 256, SMEM_BYTES>>>(x, out);
}